// round 3
// baseline (speedup 1.0000x reference)
#include <cuda_runtime.h>
#include <math.h>

#define NSAMP 1048576
#define NHOPS 1904                 // NSAMP/551 + 1
#define LBLK 64                    // output samples per sequential thread
#define IH 132                     // warmup (128) + FIR history (4)
#define ISTEPS (LBLK + IH)         // 196
#define NGRP (ISTEPS / 4)          // 49
#define NT (NSAMP / LBLK)          // 16384 sequential threads
#define KTAP 16                    // biquad truncated impulse length (|pole|~0.1)
#define TI 32                      // t-columns per kB tile
#define BSAMP (LBLK * TI + IH)     // 2180 samples staged per kB tile
#define DPOS (1903.0f / 1048575.0f)

// ---- scratch (no runtime allocation allowed) ----
__device__ float  g_taps[KTAP];
__device__ float  g_coef[(NHOPS + 2) * 9];      // per-hop: cb0..cb4, cd1..cd4
__device__ float4 g_h1T[NGRP * NT];             // h1 transposed: [group][t]{4 i's}

// ============================================================
// Kernel A: per-hop LFO -> MLP -> p -> allpass coeffs; biquad taps
// ============================================================
__global__ void kA(const float* __restrict__ g2,
                   const float* __restrict__ depth, const float* __restrict__ bias,
                   const float* __restrict__ om,    const float* __restrict__ phi,
                   const float* __restrict__ rl,
                   const float* __restrict__ Win,   const float* __restrict__ bin,
                   const float* __restrict__ Wh,    const float* __restrict__ bh,
                   const float* __restrict__ Wout,  const float* __restrict__ bout,
                   const float* __restrict__ bqdc,  const float* __restrict__ bqff,
                   const float* __restrict__ bqfb,
                   float* __restrict__ out, int out_size)
{
    int t = blockIdx.x * blockDim.x + threadIdx.x;

    if (blockIdx.x == 0 && threadIdx.x == 0) {
        // biquad taps: g = conv(b, impulse of 1/A). |poles|=sqrt(a2)~0.1 -> K=16 exact to fp32
        float a1 = 2.f * tanhf(bqfb[0]);
        float a2 = ((2.f - fabsf(a1)) * tanhf(bqfb[1]) + fabsf(a1)) * 0.5f;
        float b0 = bqdc[0], b1 = bqff[0], b2 = bqff[1];
        float hm1 = 0.f, hm2 = 0.f;
        for (int k = 0; k < KTAP; k++) {
            float ha = (k == 0 ? 1.f : 0.f) - a1 * hm1 - a2 * hm2;
            g_taps[k] = b0 * ha + b1 * hm1 + b2 * hm2;
            hm2 = hm1; hm1 = ha;
        }
    }
    if (t >= NHOPS) return;

    float tf = (float)t;
    float r  = 1.f / (1.f + expf(-rl[0]));
    float amp = expf(tf * logf(r));
    float ph  = om[0] * tf + phi[0];
    float l0 = amp * cosf(ph), l1 = amp * sinf(ph);

    float h[16];
#pragma unroll
    for (int j = 0; j < 16; j++)
        h[j] = tanhf(fmaf(l0, Win[j], fmaf(l1, Win[16 + j], bin[j])));
    for (int l = 0; l < 2; l++) {
        float nh[16];
#pragma unroll
        for (int j = 0; j < 16; j++) {
            float acc = bh[l * 16 + j];
#pragma unroll
            for (int i = 0; i < 16; i++) acc = fmaf(h[i], Wh[(l * 16 + i) * 16 + j], acc);
            nh[j] = tanhf(acc);
        }
#pragma unroll
        for (int j = 0; j < 16; j++) h[j] = nh[j];
    }
    float acc = bout[0];
#pragma unroll
    for (int i = 0; i < 16; i++) acc = fmaf(h[i], Wout[i], acc);
    float ws = tanhf(acc);

    float d  = bias[0] + depth[0] * 0.5f * (1.f + ws);
    float td = tanf(d);
    float p  = tanhf((1.f - td) / (1.f + td));

    float p2 = p * p, p3 = p2 * p, p4 = p2 * p2;
    float bap[5] = { p4, -4.f * p3, 6.f * p2, -4.f * p, 1.f };
    float aap[5] = { 1.f, -4.f * p, 6.f * p2, -4.f * p3, p4 };
    float ga  = fabsf(g2[0]);
    float inv = 1.f / (aap[0] - ga * bap[0]);
    float* cc = &g_coef[t * 9];
#pragma unroll
    for (int k = 0; k < 5; k++) cc[k] = bap[k] * inv;
#pragma unroll
    for (int k = 1; k < 5; k++) cc[4 + k] = (aap[k] - ga * bap[k]) * inv;

    if (out_size >= NSAMP + NHOPS) out[NSAMP + t] = p;
}

// ============================================================
// Kernel B: h1 = 16-tap FIR of x, write transposed [group][t] float4 layout
// ============================================================
__global__ void kB(const float* __restrict__ x)
{
    __shared__ float sh[BSAMP + BSAMP / 64 + 2];
    int t0    = blockIdx.x * TI;
    int nbase = t0 * LBLK - IH;

    float tp[KTAP];
#pragma unroll
    for (int k = 0; k < KTAP; k++) tp[k] = g_taps[k];

    for (int j = threadIdx.x; j < BSAMP; j += blockDim.x) {
        int n = nbase + j;
        float acc = 0.f;
        if (n >= KTAP - 1) {
#pragma unroll
            for (int k = 0; k < KTAP; k++) acc = fmaf(tp[k], __ldg(&x[n - k]), acc);
        } else if (n >= 0) {
            for (int k = 0; k <= n && k < KTAP; k++) acc = fmaf(tp[k], x[n - k], acc);
        }
        sh[j + (j >> 6)] = acc;
    }
    __syncthreads();

    float* h1T = (float*)g_h1T;
    for (int u = threadIdx.x; u < ISTEPS * TI; u += blockDim.x) {
        int gi   = u >> 7;            // 128 = TI*4 elems per group
        int tloc = (u >> 2) & (TI - 1);
        int s    = u & 3;
        int i    = gi * 4 + s;
        int li   = tloc * LBLK + i;
        h1T[(size_t)(gi * NT + t0 + tloc) * 4 + s] = sh[li + (li >> 6)];
    }
}

// ============================================================
// Kernel C: per-thread TV-FIR + order-4 TV-IIR with 128-sample warmup
// ============================================================
__global__ void __launch_bounds__(128, 1) kC(const float* __restrict__ g1,
                                             float* __restrict__ out)
{
    __shared__ float sh[128 * 65];
    int tl = threadIdx.x;
    int t  = blockIdx.x * 128 + tl;
    float g1v = g1[0];

    const float4* hp = g_h1T + t;
    float4 pf0 = hp[0];
    float4 pf1 = hp[NT];
    float4 pf2 = hp[2 * NT];

    int   n0  = t * LBLK - IH;
    float fi  = (float)n0;
    float pos = fi * DPOS;
    int i0 = (int)floorf(pos);
    i0 = max(0, min(i0, NHOPS - 2));
    float i0f = (float)i0;

    float b0,b1,b2,b3,b4,bd1,bd2,bd3,bd4;
    float d0,d1,d2,d3,d4,dd1,dd2,dd3,dd4;
#define RELOAD() do {                                              \
        const float* c0 = g_coef + i0 * 9;                         \
        b0=c0[0]; b1=c0[1]; b2=c0[2]; b3=c0[3]; b4=c0[4];          \
        bd1=c0[5]; bd2=c0[6]; bd3=c0[7]; bd4=c0[8];                \
        d0=c0[9]-b0; d1=c0[10]-b1; d2=c0[11]-b2;                   \
        d3=c0[12]-b3; d4=c0[13]-b4;                                \
        dd1=c0[14]-bd1; dd2=c0[15]-bd2;                            \
        dd3=c0[16]-bd3; dd4=c0[17]-bd4;                            \
    } while (0)
    RELOAD();

    float h0 = 0.f, h1v = 0.f, h2 = 0.f, h3 = 0.f;   // h1[n-1..n-4]
    float y1 = 0.f, y2 = 0.f, y3 = 0.f, y4 = 0.f;

#pragma unroll 1
    for (int g = 0; g < NGRP; g++) {
        float4 cur = pf0;
        pf0 = pf1; pf1 = pf2;
        pf2 = (g + 3 < NGRP) ? hp[(g + 3) * NT] : make_float4(0.f, 0.f, 0.f, 0.f);
#pragma unroll
        for (int s = 0; s < 4; s++) {
            float hn = (s == 0) ? cur.x : (s == 1) ? cur.y : (s == 2) ? cur.z : cur.w;
            float frac = fmaf(fi, DPOS, -i0f);
            if (frac >= 1.f && i0 < NHOPS - 2) { i0++; i0f += 1.f; frac -= 1.f; RELOAD(); }
            float cb0 = fmaf(frac, d0, b0);
            float cb1 = fmaf(frac, d1, b1);
            float cb2 = fmaf(frac, d2, b2);
            float cb3 = fmaf(frac, d3, b3);
            float cb4 = fmaf(frac, d4, b4);
            float cd1 = fmaf(frac, dd1, bd1);
            float cd2 = fmaf(frac, dd2, bd2);
            float cd3 = fmaf(frac, dd3, bd3);
            float cd4 = fmaf(frac, dd4, bd4);
            float v = cb0 * hn;
            v = fmaf(cb1, h0, v); v = fmaf(cb2, h1v, v);
            v = fmaf(cb3, h2, v); v = fmaf(cb4, h3, v);
            float a = v;
            a = fmaf(-cd4, y4, a); a = fmaf(-cd3, y3, a); a = fmaf(-cd2, y2, a);
            float y = fmaf(-cd1, y1, a);      // only this FMA is on the serial chain
            y4 = y3; y3 = y2; y2 = y1; y1 = y;
            h3 = h2; h2 = h1v; h1v = h0; h0 = hn;
            int i = g * 4 + s;
            if (i >= IH) sh[tl * 65 + (i - IH)] = fmaf(g1v, hn, y);
            fi += 1.f;
        }
    }
    __syncthreads();
    int base = blockIdx.x * 128 * LBLK;
    for (int j = tl; j < 128 * LBLK; j += 128)
        out[base + j] = sh[(j >> 6) * 65 + (j & 63)];
#undef RELOAD
}

// ============================================================
extern "C" void kernel_launch(void* const* d_in, const int* in_sizes, int n_in,
                              void* d_out, int out_size)
{
    const float* x    = (const float*)d_in[0];
    const float* g1   = (const float*)d_in[1];
    const float* g2   = (const float*)d_in[2];
    const float* dep  = (const float*)d_in[3];
    const float* bia  = (const float*)d_in[4];
    const float* om   = (const float*)d_in[5];
    const float* phi  = (const float*)d_in[6];
    const float* rl   = (const float*)d_in[7];
    const float* Win  = (const float*)d_in[8];
    const float* bin  = (const float*)d_in[9];
    const float* Wh   = (const float*)d_in[10];
    const float* bh   = (const float*)d_in[11];
    const float* Wout = (const float*)d_in[12];
    const float* bout = (const float*)d_in[13];
    const float* bqdc = (const float*)d_in[14];
    const float* bqff = (const float*)d_in[15];
    const float* bqfb = (const float*)d_in[16];
    float* out = (float*)d_out;

    kA<<<(NHOPS + 127) / 128, 128>>>(g2, dep, bia, om, phi, rl, Win, bin, Wh, bh,
                                     Wout, bout, bqdc, bqff, bqfb, out, out_size);
    kB<<<NT / TI, 256>>>(x);
    kC<<<NT / 128, 128>>>(g1, out);
}

// round 4
// speedup vs baseline: 1.2889x; 1.2889x over previous
#include <cuda_runtime.h>
#include <math.h>

#define NSAMP 1048576
#define NHOPS 1904                 // NSAMP/551 + 1
#define LBLK 64                    // output samples per sequential thread
#define IH 104                     // warmup (100) + FIR history (4); poles <=0.72 -> 0.72^100 ~ 5e-15
#define ISTEPS (LBLK + IH)         // 168
#define NT (NSAMP / LBLK)          // 16384 sequential threads
#define KTAP 16                    // biquad truncated impulse length (|pole|~0.1)
#define BT 128                     // threads per kC block
#define NB (NT / BT)               // 128 blocks
#define BOUT (BT * LBLK)           // 8192 outputs per block
#define HBUF (BOUT + IH)           // 8296 h1 samples per block
#define XBUF (HBUF + KTAP - 1)     // 8311 x samples per block
#define SXSZ 8320                  // max(XBUF, BOUT + BOUT/64) : x stage, reused as out stage
#define SHSZ (HBUF + HBUF / 64 + 4)// padded h1 buffer
#define SMEM_F (SXSZ + SHSZ)
#define DPOS (1903.0f / 1048575.0f)

// ---- scratch (no runtime allocation allowed) ----
__device__ float g_coef[(NHOPS + 2) * 9];       // per-hop: cb0..cb4, cd1..cd4

// ============================================================
// Kernel A: per-hop LFO -> MLP -> p -> allpass coeffs (weights in SMEM)
// ============================================================
__global__ void kA(const float* __restrict__ g2,
                   const float* __restrict__ depth, const float* __restrict__ bias,
                   const float* __restrict__ om,    const float* __restrict__ phi,
                   const float* __restrict__ rl,
                   const float* __restrict__ Win,   const float* __restrict__ bin,
                   const float* __restrict__ Wh,    const float* __restrict__ bh,
                   const float* __restrict__ Wout,  const float* __restrict__ bout,
                   float* __restrict__ out, int out_size)
{
    __shared__ float sWin[32], sbin[16], sWh[512], sbh[32], sWout[16], sbout[1];
    int tl = threadIdx.x;
    for (int j = tl; j < 32;  j += BT) sWin[j]  = Win[j];
    for (int j = tl; j < 16;  j += BT) sbin[j]  = bin[j];
    for (int j = tl; j < 512; j += BT) sWh[j]   = Wh[j];
    for (int j = tl; j < 32;  j += BT) sbh[j]   = bh[j];
    for (int j = tl; j < 16;  j += BT) sWout[j] = Wout[j];
    if (tl == 0) sbout[0] = bout[0];
    __syncthreads();

    int t = blockIdx.x * blockDim.x + tl;
    if (t >= NHOPS) return;

    float tf = (float)t;
    float r  = 1.f / (1.f + expf(-rl[0]));
    float amp = expf(tf * logf(r));
    float ph  = om[0] * tf + phi[0];
    float l0 = amp * cosf(ph), l1 = amp * sinf(ph);

    float h[16];
#pragma unroll
    for (int j = 0; j < 16; j++)
        h[j] = tanhf(fmaf(l0, sWin[j], fmaf(l1, sWin[16 + j], sbin[j])));
#pragma unroll
    for (int l = 0; l < 2; l++) {
        float nh[16];
#pragma unroll
        for (int j = 0; j < 16; j++) {
            float acc = sbh[l * 16 + j];
#pragma unroll
            for (int i = 0; i < 16; i++) acc = fmaf(h[i], sWh[l * 256 + i * 16 + j], acc);
            nh[j] = tanhf(acc);
        }
#pragma unroll
        for (int j = 0; j < 16; j++) h[j] = nh[j];
    }
    float acc = sbout[0];
#pragma unroll
    for (int i = 0; i < 16; i++) acc = fmaf(h[i], sWout[i], acc);
    float ws = tanhf(acc);

    float d  = bias[0] + depth[0] * 0.5f * (1.f + ws);
    float td = tanf(d);
    float p  = tanhf((1.f - td) / (1.f + td));

    float p2 = p * p, p3 = p2 * p, p4 = p2 * p2;
    float bap[5] = { p4, -4.f * p3, 6.f * p2, -4.f * p, 1.f };
    float aap[5] = { 1.f, -4.f * p, 6.f * p2, -4.f * p3, p4 };
    float ga  = fabsf(g2[0]);
    float inv = 1.f / (aap[0] - ga * bap[0]);
    float* cc = &g_coef[t * 9];
#pragma unroll
    for (int k = 0; k < 5; k++) cc[k] = bap[k] * inv;
#pragma unroll
    for (int k = 1; k < 5; k++) cc[4 + k] = (aap[k] - ga * bap[k]) * inv;

    if (out_size >= NSAMP + NHOPS) out[NSAMP + t] = p;
}

// ============================================================
// Kernel C (fused): x -> biquad-FIR h1 (SMEM) -> TV-FIR + order-4 TV-IIR
// ============================================================
__global__ void __launch_bounds__(BT) kC(const float* __restrict__ x,
                                         const float* __restrict__ g1,
                                         const float* __restrict__ bqdc,
                                         const float* __restrict__ bqff,
                                         const float* __restrict__ bqfb,
                                         float* __restrict__ out)
{
    extern __shared__ float smem[];
    float* sX = smem;            // x staging, later output staging (padded idx + idx>>6)
    float* sH = smem + SXSZ;     // h1 staging (padded idx + idx>>6)

    int tl = threadIdx.x;
    int t  = blockIdx.x * BT + tl;
    int n0 = blockIdx.x * BOUT - IH;     // sample index of sH[0]

    // ---- stage x: [n0-15, n0 + HBUF), zeros for n<0 ----
    for (int j = tl; j < XBUF; j += BT) {
        int n = n0 - (KTAP - 1) + j;
        sX[j] = (n >= 0) ? x[n] : 0.f;
    }

    // ---- biquad truncated-impulse taps (uniform per-thread compute) ----
    float tp[KTAP];
    {
        float a1 = 2.f * tanhf(bqfb[0]);
        float a2 = ((2.f - fabsf(a1)) * tanhf(bqfb[1]) + fabsf(a1)) * 0.5f;
        float b0 = bqdc[0], b1 = bqff[0], b2 = bqff[1];
        float hm1 = 0.f, hm2 = 0.f;
#pragma unroll
        for (int k = 0; k < KTAP; k++) {
            float ha = (k == 0 ? 1.f : 0.f) - a1 * hm1 - a2 * hm2;
            tp[k] = b0 * ha + b1 * hm1 + b2 * hm2;
            hm2 = hm1; hm1 = ha;
        }
    }
    float g1v = g1[0];
    __syncthreads();

    // ---- h1 = 16-tap FIR; thread covers 65 consecutive outputs (stride-65 -> conflict free) ----
    {
        int o0 = tl * 65;
        int oe = min(o0 + 65, HBUF);
        for (int j = o0; j < oe; j++) {
            float acc = 0.f;
#pragma unroll
            for (int k = 0; k < KTAP; k++)
                acc = fmaf(tp[k], sX[j + (KTAP - 1) - k], acc);  // x[n-k]
            sH[j + (j >> 6)] = acc;
        }
    }
    __syncthreads();

    // ---- interp coefficient setup ----
    int   ns  = t * LBLK - IH;
    float fi  = (float)ns;
    int i0 = (int)floorf(fi * DPOS);
    i0 = max(0, min(i0, NHOPS - 2));
    float i0f = (float)i0;

    float b0,b1,b2,b3,b4,bd1,bd2,bd3,bd4;
    float d0,d1,d2,d3,d4,dd1,dd2,dd3,dd4;
#define RELOAD() do {                                              \
        const float* c0 = g_coef + i0 * 9;                         \
        b0=c0[0]; b1=c0[1]; b2=c0[2]; b3=c0[3]; b4=c0[4];          \
        bd1=c0[5]; bd2=c0[6]; bd3=c0[7]; bd4=c0[8];                \
        d0=c0[9]-b0; d1=c0[10]-b1; d2=c0[11]-b2;                   \
        d3=c0[12]-b3; d4=c0[13]-b4;                                \
        dd1=c0[14]-bd1; dd2=c0[15]-bd2;                            \
        dd3=c0[16]-bd3; dd4=c0[17]-bd4;                            \
    } while (0)
    RELOAD();

    float h0 = 0.f, h1v = 0.f, h2 = 0.f, h3 = 0.f;   // h1[n-1..n-4]
    float y1 = 0.f, y2 = 0.f, y3 = 0.f, y4 = 0.f;

#define STEP(i, DO_STORE) do {                                         \
        int li = tl * LBLK + (i);                                      \
        float hn = sH[li + (li >> 6)];                                 \
        float frac = fmaf(fi, DPOS, -i0f);                             \
        if (frac >= 1.f && i0 < NHOPS - 2) {                           \
            i0++; i0f += 1.f; frac -= 1.f; RELOAD();                   \
        }                                                              \
        float cb0 = fmaf(frac, d0, b0);                                \
        float cb1 = fmaf(frac, d1, b1);                                \
        float cb2 = fmaf(frac, d2, b2);                                \
        float cb3 = fmaf(frac, d3, b3);                                \
        float cb4 = fmaf(frac, d4, b4);                                \
        float cd1 = fmaf(frac, dd1, bd1);                              \
        float cd2 = fmaf(frac, dd2, bd2);                              \
        float cd3 = fmaf(frac, dd3, bd3);                              \
        float cd4 = fmaf(frac, dd4, bd4);                              \
        float v = cb0 * hn;                                            \
        v = fmaf(cb1, h0, v); v = fmaf(cb2, h1v, v);                   \
        v = fmaf(cb3, h2, v); v = fmaf(cb4, h3, v);                    \
        float a = v;                                                   \
        a = fmaf(-cd4, y4, a); a = fmaf(-cd3, y3, a);                  \
        a = fmaf(-cd2, y2, a);                                         \
        float y = fmaf(-cd1, y1, a);                                   \
        y4 = y3; y3 = y2; y2 = y1; y1 = y;                             \
        h3 = h2; h2 = h1v; h1v = h0; h0 = hn;                          \
        if (DO_STORE) {                                                \
            int o = li - IH;                                           \
            sX[o + (o >> 6)] = fmaf(g1v, hn, y);                       \
        }                                                              \
        fi += 1.f;                                                     \
    } while (0)

    int i = 0;
#pragma unroll 4
    for (; i < IH; i++) STEP(i, 0);          // warmup: no store
#pragma unroll 4
    for (; i < ISTEPS; i++) STEP(i, 1);      // live region
#undef STEP
#undef RELOAD

    __syncthreads();
    int base = blockIdx.x * BOUT;
    for (int j = tl; j < BOUT; j += BT)
        out[base + j] = sX[j + (j >> 6)];
}

// ============================================================
extern "C" void kernel_launch(void* const* d_in, const int* in_sizes, int n_in,
                              void* d_out, int out_size)
{
    const float* x    = (const float*)d_in[0];
    const float* g1   = (const float*)d_in[1];
    const float* g2   = (const float*)d_in[2];
    const float* dep  = (const float*)d_in[3];
    const float* bia  = (const float*)d_in[4];
    const float* om   = (const float*)d_in[5];
    const float* phi  = (const float*)d_in[6];
    const float* rl   = (const float*)d_in[7];
    const float* Win  = (const float*)d_in[8];
    const float* bin  = (const float*)d_in[9];
    const float* Wh   = (const float*)d_in[10];
    const float* bh   = (const float*)d_in[11];
    const float* Wout = (const float*)d_in[12];
    const float* bout = (const float*)d_in[13];
    const float* bqdc = (const float*)d_in[14];
    const float* bqff = (const float*)d_in[15];
    const float* bqfb = (const float*)d_in[16];
    float* out = (float*)d_out;

    cudaFuncSetAttribute(kC, cudaFuncAttributeMaxDynamicSharedMemorySize,
                         SMEM_F * (int)sizeof(float));

    kA<<<(NHOPS + BT - 1) / BT, BT>>>(g2, dep, bia, om, phi, rl, Win, bin, Wh, bh,
                                      Wout, bout, out, out_size);
    kC<<<NB, BT, SMEM_F * (int)sizeof(float)>>>(x, g1, bqdc, bqff, bqfb, out);
}

// round 6
// speedup vs baseline: 1.9780x; 1.5347x over previous
#include <cuda_runtime.h>
#include <math.h>

#define NSAMP 1048576
#define NHOPS 1904                 // NSAMP/551 + 1
#define LBLK 32                    // output samples per sequential thread
#define IH 84                      // warmup (80) + FIR history (4); k^3*0.72^80/6 ~ 4e-7
#define ISTEPS (LBLK + IH)         // 116
#define NQUAD (ISTEPS / 4)         // 29
#define WQUAD (IH / 4)             // 21 warmup quads
#define BT 64                      // threads per block (2 warps)
#define BOUT (BT * LBLK)           // 2048 outputs per block
#define NB (NSAMP / BOUT)          // 512 blocks
#define HBUF (BOUT + IH)           // 2132 h1 samples needed
#define XBUF (HBUF + 15)           // 2147 x samples staged
#define FPL 67                     // FIR outputs per warp-1 lane (32*67=2144>=2132)
#define KTAP 16
#define DPOS (1903.0f / 1048575.0f)

// ============================================================
// Single fused kernel: stage x -> {block-local hop MLP || biquad-FIR h1}
//                      -> TV-FIR + order-4 TV-IIR -> out
// ============================================================
__global__ void __launch_bounds__(BT) phaser(
    const float* __restrict__ x,
    const float* __restrict__ g1,   const float* __restrict__ g2,
    const float* __restrict__ depth,const float* __restrict__ bias,
    const float* __restrict__ om,   const float* __restrict__ phi,
    const float* __restrict__ rl,
    const float* __restrict__ Win,  const float* __restrict__ bin,
    const float* __restrict__ Wh,   const float* __restrict__ bh,
    const float* __restrict__ Wout, const float* __restrict__ bout,
    const float* __restrict__ bqdc, const float* __restrict__ bqff,
    const float* __restrict__ bqfb,
    float* __restrict__ out, int out_size)
{
    __shared__ float sX[2176];     // x stage; later output stage (idx o+(o>>5))
    __shared__ float sH[2212];     // h1 (idx j+(j>>5))
    __shared__ float sC[80];       // 8 hop slots x 9 coefs {cb0..4, cd1..4}
    __shared__ float sW[612];      // Win 0 | bin 32 | Wh 48 | bh 560 | Wout 592 | bout 608

    int tid = threadIdx.x;
    int b   = blockIdx.x;
    int n0  = b * BOUT - IH;       // sample index of sH[0]
    float g1v = g1[0];

    // ---- phase 0: stage x and MLP weights (all threads, coalesced) ----
    for (int j = tid; j < XBUF; j += BT) {
        int n = n0 - (KTAP - 1) + j;
        sX[j] = (n >= 0) ? x[n] : 0.f;
    }
    for (int j = tid; j < 32;  j += BT) sW[j]       = Win[j];
    for (int j = tid; j < 16;  j += BT) sW[32 + j]  = bin[j];
    for (int j = tid; j < 512; j += BT) sW[48 + j]  = Wh[j];
    for (int j = tid; j < 32;  j += BT) sW[560 + j] = bh[j];
    for (int j = tid; j < 16;  j += BT) sW[592 + j] = Wout[j];
    if (tid == 0) sW[608] = bout[0];

    int h_lo = (int)floorf((float)n0 * DPOS);
    if (h_lo < 0) h_lo = 0;
    __syncthreads();

    // ---- phase 1: warp0 lanes 0-7 = hop MLP ; warp1 = FIR ----
    if (tid < 8) {
        int hop = h_lo + tid; if (hop > NHOPS - 1) hop = NHOPS - 1;
        float tf = (float)hop;
        float r  = 1.f / (1.f + expf(-__ldg(&rl[0])));
        float amp = expf(tf * logf(r));
        float ph  = __ldg(&om[0]) * tf + __ldg(&phi[0]);
        float l0 = amp * cosf(ph), l1 = amp * sinf(ph);

        float h[16];
#pragma unroll
        for (int j = 0; j < 16; j++)
            h[j] = tanhf(fmaf(l0, sW[j], fmaf(l1, sW[16 + j], sW[32 + j])));
#pragma unroll
        for (int l = 0; l < 2; l++) {
            float nh[16];
#pragma unroll
            for (int j = 0; j < 16; j++) {
                float acc = sW[560 + l * 16 + j];
#pragma unroll
                for (int i = 0; i < 16; i++)
                    acc = fmaf(h[i], sW[48 + l * 256 + i * 16 + j], acc);
                nh[j] = tanhf(acc);
            }
#pragma unroll
            for (int j = 0; j < 16; j++) h[j] = nh[j];
        }
        float acc = sW[608];
#pragma unroll
        for (int i = 0; i < 16; i++) acc = fmaf(h[i], sW[592 + i], acc);
        float ws = tanhf(acc);

        float dd = __ldg(&bias[0]) + __ldg(&depth[0]) * 0.5f * (1.f + ws);
        float td = tanf(dd);
        float p  = tanhf((1.f - td) / (1.f + td));

        float p2 = p * p, p3 = p2 * p, p4 = p2 * p2;
        float bap[5] = { p4, -4.f * p3, 6.f * p2, -4.f * p, 1.f };
        float aap[5] = { 1.f, -4.f * p, 6.f * p2, -4.f * p3, p4 };
        float ga  = fabsf(__ldg(&g2[0]));
        float inv = 1.f / (1.f - ga * p4);
        float* cc = &sC[tid * 9];
#pragma unroll
        for (int k = 0; k < 5; k++) cc[k] = bap[k] * inv;
#pragma unroll
        for (int k = 1; k < 5; k++) cc[4 + k] = (aap[k] - ga * bap[k]) * inv;

        if (out_size >= NSAMP + NHOPS) out[NSAMP + hop] = p;
    } else if (tid >= 32) {
        // biquad truncated-impulse taps
        float a1c = 2.f * tanhf(__ldg(&bqfb[0]));
        float a2c = ((2.f - fabsf(a1c)) * tanhf(__ldg(&bqfb[1])) + fabsf(a1c)) * 0.5f;
        float bb0 = __ldg(&bqdc[0]), bb1 = __ldg(&bqff[0]), bb2 = __ldg(&bqff[1]);
        float tp[KTAP];
        float hm1 = 0.f, hm2 = 0.f;
#pragma unroll
        for (int k = 0; k < KTAP; k++) {
            float ha = (k == 0 ? 1.f : 0.f) - a1c * hm1 - a2c * hm2;
            tp[k] = bb0 * ha + bb1 * hm1 + bb2 * hm2;
            hm2 = hm1; hm1 = ha;
        }
        // rolling-window 16-tap FIR: h1[j] = sum_m tp[15-m]*sX[j+m]
        int lane = tid - 32;
        int o0 = lane * FPL;
        float w[16];
#pragma unroll
        for (int k = 0; k < 16; k++) w[k] = sX[o0 + k];
#pragma unroll
        for (int c = 0; c < 4; c++) {
#pragma unroll
            for (int s = 0; s < 16; s++) {
                int jj = o0 + c * 16 + s;
                float acc = 0.f;
#pragma unroll
                for (int m = 0; m < 16; m++)
                    acc = fmaf(tp[15 - m], w[(s + m) & 15], acc);
                sH[jj + (jj >> 5)] = acc;
                w[s] = sX[jj + 16];
            }
        }
#pragma unroll
        for (int s = 0; s < 3; s++) {          // tail: 67 = 64 + 3
            int jj = o0 + 64 + s;
            float acc = 0.f;
#pragma unroll
            for (int m = 0; m < 16; m++)
                acc = fmaf(tp[15 - m], w[(s + m) & 15], acc);
            sH[jj + (jj >> 5)] = acc;
            w[s] = sX[jj + 16];                // FIX: keep the ring fresh in the tail
        }
    }
    __syncthreads();

    // ---- phase 2: TV-FIR + order-4 TV-IIR recurrence ----
    int   li0 = tid * LBLK;
    float fi  = (float)(n0 + li0);
    int i0 = (int)floorf(fi * DPOS);
    i0 = max(0, min(i0, NHOPS - 2));
    float i0f = (float)i0;

    float b0,b1,b2,b3,b4,bd1,bd2,bd3,bd4;
    float d0,d1,d2,d3,d4,dd1,dd2,dd3,dd4;
#define RELOAD() do {                                              \
        const float* c0 = sC + (i0 - h_lo) * 9;                    \
        b0=c0[0]; b1=c0[1]; b2=c0[2]; b3=c0[3]; b4=c0[4];          \
        bd1=c0[5]; bd2=c0[6]; bd3=c0[7]; bd4=c0[8];                \
        d0=c0[9]-b0; d1=c0[10]-b1; d2=c0[11]-b2;                   \
        d3=c0[12]-b3; d4=c0[13]-b4;                                \
        dd1=c0[14]-bd1; dd2=c0[15]-bd2;                            \
        dd3=c0[16]-bd3; dd4=c0[17]-bd4;                            \
    } while (0)
    RELOAD();

    float h0 = 0.f, h1v = 0.f, h2 = 0.f, h3 = 0.f;
    float y1 = 0.f, y2 = 0.f, y3 = 0.f, y4 = 0.f;

    // Per-sample interpolation; knot-crossing checked once per quad.
    // Late crossing (<=3 samples) = linear extrapolation with frac in (1, 1.006):
    // error is a second-difference of the coef trajectory (~1e-7) -- negligible.
#define QUAD(GQ, STORE) do {                                           \
        float frac = fmaf(fi, DPOS, -i0f);                             \
        if (frac >= 1.f && i0 < NHOPS - 2) {                           \
            i0++; i0f += 1.f; frac -= 1.f; RELOAD();                   \
        }                                                              \
        _Pragma("unroll")                                              \
        for (int s = 0; s < 4; s++) {                                  \
            int li = li0 + (GQ) * 4 + s;                               \
            float hn = sH[li + (li >> 5)];                             \
            float cb0 = fmaf(frac, d0, b0);                            \
            float cb1 = fmaf(frac, d1, b1);                            \
            float cb2 = fmaf(frac, d2, b2);                            \
            float cb3 = fmaf(frac, d3, b3);                            \
            float cb4 = fmaf(frac, d4, b4);                            \
            float cd1 = fmaf(frac, dd1, bd1);                          \
            float cd2 = fmaf(frac, dd2, bd2);                          \
            float cd3 = fmaf(frac, dd3, bd3);                          \
            float cd4 = fmaf(frac, dd4, bd4);                          \
            float v = cb0 * hn;                                        \
            v = fmaf(cb1, h0, v); v = fmaf(cb2, h1v, v);               \
            v = fmaf(cb3, h2, v); v = fmaf(cb4, h3, v);                \
            float a = fmaf(-cd4, y4, v);                               \
            a = fmaf(-cd3, y3, a); a = fmaf(-cd2, y2, a);              \
            float y = fmaf(-cd1, y1, a);                               \
            y4 = y3; y3 = y2; y2 = y1; y1 = y;                         \
            h3 = h2; h2 = h1v; h1v = h0; h0 = hn;                      \
            if (STORE) {                                               \
                int o = li - IH;                                       \
                sX[o + (o >> 5)] = fmaf(g1v, hn, y);                   \
            }                                                          \
            frac += DPOS;                                              \
        }                                                              \
        fi += 4.f;                                                     \
    } while (0)

#pragma unroll 1
    for (int g = 0; g < WQUAD; g++) QUAD(g, 0);     // warmup
#pragma unroll 1
    for (int g = WQUAD; g < NQUAD; g++) QUAD(g, 1); // live
#undef QUAD
#undef RELOAD

    __syncthreads();
    int base = b * BOUT;
    for (int j = tid; j < BOUT; j += BT)
        out[base + j] = sX[j + (j >> 5)];
}

// ============================================================
extern "C" void kernel_launch(void* const* d_in, const int* in_sizes, int n_in,
                              void* d_out, int out_size)
{
    const float* x    = (const float*)d_in[0];
    const float* g1   = (const float*)d_in[1];
    const float* g2   = (const float*)d_in[2];
    const float* dep  = (const float*)d_in[3];
    const float* bia  = (const float*)d_in[4];
    const float* om   = (const float*)d_in[5];
    const float* phi  = (const float*)d_in[6];
    const float* rl   = (const float*)d_in[7];
    const float* Win  = (const float*)d_in[8];
    const float* bin  = (const float*)d_in[9];
    const float* Wh   = (const float*)d_in[10];
    const float* bh   = (const float*)d_in[11];
    const float* Wout = (const float*)d_in[12];
    const float* bout = (const float*)d_in[13];
    const float* bqdc = (const float*)d_in[14];
    const float* bqff = (const float*)d_in[15];
    const float* bqfb = (const float*)d_in[16];
    float* out = (float*)d_out;

    phaser<<<NB, BT>>>(x, g1, g2, dep, bia, om, phi, rl,
                       Win, bin, Wh, bh, Wout, bout, bqdc, bqff, bqfb,
                       out, out_size);
}